// round 1
// baseline (speedup 1.0000x reference)
#include <cuda_runtime.h>
#include <math.h>

#define COL 14
#define NJ 23
#define PAIR_ELEMS (COL * COL)   // 196
#define WARPS_PER_BLOCK 8
#define BLOCK_THREADS (WARPS_PER_BLOCK * 32)

__device__ float g_M[PAIR_ELEMS];  // M[out][i], row-major 14x14

// Build the gaussian-filter matrix exactly like the reference:
// weights in double, normalized in double, cast to f32, accumulated in f32 in k order.
__global__ void init_M_kernel() {
    int tid = threadIdx.x;
    if (tid >= PAIR_ELEMS) return;
    double wd[9];
    double s = 0.0;
    #pragma unroll
    for (int k = 0; k < 9; k++) {
        double x = (double)(k - 4);
        wd[k] = exp(-0.5 * x * x);
        s += wd[k];
    }
    float wf[9];
    #pragma unroll
    for (int k = 0; k < 9; k++) wf[k] = (float)(wd[k] / s);

    int out = tid / COL;
    int i   = tid % COL;
    float m = 0.0f;
    #pragma unroll
    for (int k = -4; k <= 4; k++) {
        int ii = ((out + k) % (2 * COL) + 2 * COL) % (2 * COL);
        if (ii >= COL) ii = 2 * COL - 1 - ii;
        if (ii == i) m += wf[k + 4];
    }
    g_M[tid] = m;
}

__global__ __launch_bounds__(BLOCK_THREADS)
void mse3d_kernel(const float* __restrict__ o,
                  const float* __restrict__ h,
                  const float* __restrict__ t,
                  const int*   __restrict__ v,
                  float* __restrict__ out,
                  int n_pairs) {
    __shared__ float Ms[PAIR_ELEMS];
    int tid = threadIdx.x;
    if (tid < PAIR_ELEMS) Ms[tid] = g_M[tid];
    __syncthreads();

    const int lane = tid & 31;
    const int warp = tid >> 5;
    const int pair = blockIdx.x * WARPS_PER_BLOCK + warp;

    float acc = 0.0f;

    if (pair < n_pairs) {
        const int b = pair / NJ;
        const int j = pair % NJ;
        const float* hp = h + (size_t)pair * PAIR_ELEMS;

        // ---- load h tile (coalesced, lane-strided), local argmax ----
        float hv[7];
        float best = -INFINITY;
        int   bidx = 0;
        #pragma unroll
        for (int i = 0; i < 7; i++) {
            int e = lane + 32 * i;
            float val = (e < PAIR_ELEMS) ? hp[e] : -INFINITY;
            hv[i] = val;
            if (val > best) { best = val; bidx = e; }  // strictly >, keeps first index
        }
        // warp argmax reduce, first-max tie-break (smaller index wins on equality)
        #pragma unroll
        for (int off = 16; off > 0; off >>= 1) {
            float ov = __shfl_down_sync(0xffffffffu, best, off);
            int   oi = __shfl_down_sync(0xffffffffu, bidx, off);
            if (ov > best || (ov == best && oi < bidx)) { best = ov; bidx = oi; }
        }
        bidx = __shfl_sync(0xffffffffu, bidx, 0);
        const int ay = bidx / COL;
        const int ax = bidx % COL;

        // ---- target parameters ----
        const float t0 = t[(size_t)pair * 3 + 0];
        const float t1 = t[(size_t)pair * 3 + 1];
        const float t2 = t[(size_t)pair * 3 + 2];
        const int xi = (int)truncf(t0 * (float)COL);
        const int yi = (int)truncf(t1 * (float)COL);
        const bool in_range = (xi >= 0) && (xi <= COL - 1) && (yi >= 0) && (yi <= COL - 1);
        const bool mask = (v[(size_t)pair * 2] == 1) && in_range;
        const int xc = min(max(xi, 0), COL - 1);
        const int yc = min(max(yi, 0), COL - 1);

        // min/max of gy = M[:,yc], gx = M[:,xc]  (all >= 0 so min/max of the
        // outer product factorizes exactly, even in float)
        float gymin = INFINITY, gymax = -INFINITY;
        float gxmin = INFINITY, gxmax = -INFINITY;
        #pragma unroll
        for (int r = 0; r < COL; r++) {
            float gyv = Ms[r * COL + yc];
            float gxv = Ms[r * COL + xc];
            gymin = fminf(gymin, gyv); gymax = fmaxf(gymax, gyv);
            gxmin = fminf(gxmin, gxv); gxmax = fmaxf(gxmax, gxv);
        }
        const float mn  = gymin * gxmin;
        const float mx  = gymax * gxmax;
        const float inv = mask ? (1.0f / (mx - mn)) : 0.0f;

        // ---- d1: sum (h - tt)^2 over the 14x14 tile ----
        float d1 = 0.0f;
        #pragma unroll
        for (int i = 0; i < 7; i++) {
            int e = lane + 32 * i;
            if (e < PAIR_ELEMS) {
                int r = e / COL;
                int c = e - r * COL;
                float ttv = (Ms[r * COL + yc] * Ms[c * COL + xc] - mn) * inv;
                float diff = hv[i] - ttv;
                d1 += diff * diff;
            }
        }
        acc = d1;

        // ---- d2: only 3 gathered values from o, done by lane 0 ----
        if (lane == 0) {
            const size_t base = (((size_t)b * (3 * NJ) + j) * COL + ay) * COL + ax;
            const float o0 = o[base];
            const float o1 = o[base + (size_t)NJ * PAIR_ELEMS];
            const float o2 = o[base + (size_t)(2 * NJ) * PAIR_ELEMS];
            const float scale = 1.0f / (float)COL;
            const float px = o0 + (float)ax * scale;
            const float py = o1 + (float)ay * scale;
            const float pz = o2;
            const float dx = px - t0;
            const float dy = py - t1;
            const float dz = pz - t2;
            acc += dx * dx + dy * dy + dz * dz;
        }
    }

    // ---- block reduction, one atomic per block ----
    #pragma unroll
    for (int off = 16; off > 0; off >>= 1)
        acc += __shfl_down_sync(0xffffffffu, acc, off);

    __shared__ float wsum[WARPS_PER_BLOCK];
    if (lane == 0) wsum[warp] = acc;
    __syncthreads();
    if (warp == 0) {
        float s = (lane < WARPS_PER_BLOCK) ? wsum[lane] : 0.0f;
        #pragma unroll
        for (int off = WARPS_PER_BLOCK / 2; off > 0; off >>= 1)
            s += __shfl_down_sync(0xffffffffu, s, off);
        if (lane == 0) atomicAdd(out, s * (1.0f / (float)NJ));
    }
}

extern "C" void kernel_launch(void* const* d_in, const int* in_sizes, int n_in,
                              void* d_out, int out_size) {
    const float* o = (const float*)d_in[0];
    const float* h = (const float*)d_in[1];
    const float* t = (const float*)d_in[2];
    const int*   v = (const int*)d_in[3];
    float* out = (float*)d_out;

    const int n_pairs = in_sizes[1] / PAIR_ELEMS;   // B * NJ from h's element count

    cudaMemsetAsync(d_out, 0, (size_t)out_size * sizeof(float));
    init_M_kernel<<<1, 256>>>();

    const int blocks = (n_pairs + WARPS_PER_BLOCK - 1) / WARPS_PER_BLOCK;
    mse3d_kernel<<<blocks, BLOCK_THREADS>>>(o, h, t, v, out, n_pairs);
}

// round 2
// speedup vs baseline: 1.2463x; 1.2463x over previous
#include <cuda_runtime.h>
#include <math.h>

#define COL 14
#define NJ 23
#define PAIR_ELEMS (COL * COL)   // 196
#define WARPS_PER_BLOCK 16
#define BLOCK_THREADS (WARPS_PER_BLOCK * 32)

__device__ float        g_sum   = 0.0f;
__device__ unsigned int g_count = 0u;

__global__ __launch_bounds__(BLOCK_THREADS)
void mse3d_kernel(const float* __restrict__ o,
                  const float* __restrict__ h,
                  const float* __restrict__ t,
                  const int*   __restrict__ v,
                  float* __restrict__ out,
                  int n_pairs) {
    // Mt[i*COL + out] = M[out][i]  (transposed: column i of M is contiguous)
    __shared__ float sMt[PAIR_ELEMS];
    __shared__ float sColMin[COL], sColMax[COL];
    __shared__ float wsum[WARPS_PER_BLOCK];

    const int tid = threadIdx.x;

    // ---- per-block gaussian matrix build (cheap: float expf) ----
    if (tid < PAIR_ELEMS) {
        float w[9];
        float s = 0.0f;
        #pragma unroll
        for (int k = 0; k < 9; k++) {
            float x = (float)(k - 4);
            w[k] = expf(-0.5f * x * x);
            s += w[k];
        }
        const float invs = 1.0f / s;
        const int outr = tid / COL;
        const int i    = tid % COL;
        float m = 0.0f;
        #pragma unroll
        for (int k = -4; k <= 4; k++) {
            int ii = (outr + k + 2 * COL) % (2 * COL);
            if (ii >= COL) ii = 2 * COL - 1 - ii;
            if (ii == i) m += w[k + 4] * invs;
        }
        sMt[i * COL + outr] = m;
    }
    __syncthreads();
    if (tid < COL) {
        float mn = INFINITY, mx = -INFINITY;
        #pragma unroll
        for (int r = 0; r < COL; r++) {
            float val = sMt[tid * COL + r];   // M[r][tid]
            mn = fminf(mn, val);
            mx = fmaxf(mx, val);
        }
        sColMin[tid] = mn;
        sColMax[tid] = mx;
    }
    __syncthreads();

    const int lane = tid & 31;
    const int warp = tid >> 5;
    const int pair = blockIdx.x * WARPS_PER_BLOCK + warp;

    float acc = 0.0f;

    if (pair < n_pairs) {
        const int b = pair / NJ;
        const int j = pair % NJ;

        // ---- vectorized load of h tile: 49 exact float4 per pair ----
        const float4* hp4 = (const float4*)(h + (size_t)pair * PAIR_ELEMS);
        const int  ia   = lane;            // always < 49
        const int  ib   = 32 + lane;
        const bool hasb = (ib < 49);       // lanes 0..16
        float4 va = hp4[ia];
        float4 vb = hasb ? hp4[ib] : make_float4(0.f, 0.f, 0.f, 0.f);

        // ---- local argmax (ascending element order, strict > keeps first) ----
        float best = va.x; int bidx = 4 * ia;
        if (va.y > best) { best = va.y; bidx = 4 * ia + 1; }
        if (va.z > best) { best = va.z; bidx = 4 * ia + 2; }
        if (va.w > best) { best = va.w; bidx = 4 * ia + 3; }
        if (hasb) {
            if (vb.x > best) { best = vb.x; bidx = 4 * ib; }
            if (vb.y > best) { best = vb.y; bidx = 4 * ib + 1; }
            if (vb.z > best) { best = vb.z; bidx = 4 * ib + 2; }
            if (vb.w > best) { best = vb.w; bidx = 4 * ib + 3; }
        }
        // warp argmax, first-occurrence tie-break
        #pragma unroll
        for (int off = 16; off > 0; off >>= 1) {
            float ov = __shfl_down_sync(0xffffffffu, best, off);
            int   oi = __shfl_down_sync(0xffffffffu, bidx, off);
            if (ov > best || (ov == best && oi < bidx)) { best = ov; bidx = oi; }
        }
        bidx = __shfl_sync(0xffffffffu, bidx, 0);
        const int ay = bidx / COL;
        const int ax = bidx % COL;

        // ---- per-pair scalars (broadcast loads) ----
        const float t0 = t[(size_t)pair * 3 + 0];
        const float t1 = t[(size_t)pair * 3 + 1];
        const float t2 = t[(size_t)pair * 3 + 2];
        const int xi = (int)truncf(t0 * (float)COL);
        const int yi = (int)truncf(t1 * (float)COL);
        const bool in_range = (xi >= 0) && (xi <= COL - 1) && (yi >= 0) && (yi <= COL - 1);
        const bool mask = (v[(size_t)pair * 2] == 1) && in_range;

        if (mask) {
            const int xc = min(max(xi, 0), COL - 1);
            const int yc = min(max(yi, 0), COL - 1);
            const float mn  = sColMin[yc] * sColMin[xc];
            const float mx  = sColMax[yc] * sColMax[xc];
            const float inv = 1.0f / (mx - mn);
            const float nb  = -mn * inv;              // ttv = gy*gx*inv + nb
            const float* gy = &sMt[yc * COL];         // gy[r] = M[r][yc]
            const float* gx = &sMt[xc * COL];         // gx[c] = M[c][xc]

            {
                int e = 4 * ia;
                int r = e / COL, c = e - (e / COL) * COL;
                float hv[4] = {va.x, va.y, va.z, va.w};
                #pragma unroll
                for (int q = 0; q < 4; q++) {
                    float ttv = fmaf(gy[r] * gx[c], inv, nb);
                    float d = hv[q] - ttv;
                    acc = fmaf(d, d, acc);
                    if (++c == COL) { c = 0; ++r; }
                }
            }
            if (hasb) {
                int e = 4 * ib;
                int r = e / COL, c = e - (e / COL) * COL;
                float hv[4] = {vb.x, vb.y, vb.z, vb.w};
                #pragma unroll
                for (int q = 0; q < 4; q++) {
                    float ttv = fmaf(gy[r] * gx[c], inv, nb);
                    float d = hv[q] - ttv;
                    acc = fmaf(d, d, acc);
                    if (++c == COL) { c = 0; ++r; }
                }
            }
        } else {
            // tt == 0 everywhere: d1 contribution is just sum(h^2)
            acc = fmaf(va.x, va.x, acc);
            acc = fmaf(va.y, va.y, acc);
            acc = fmaf(va.z, va.z, acc);
            acc = fmaf(va.w, va.w, acc);
            if (hasb) {
                acc = fmaf(vb.x, vb.x, acc);
                acc = fmaf(vb.y, vb.y, acc);
                acc = fmaf(vb.z, vb.z, acc);
                acc = fmaf(vb.w, vb.w, acc);
            }
        }

        // ---- d2: 3 gathered values from o (lane 0 only) ----
        if (lane == 0) {
            const size_t base = (((size_t)b * (3 * NJ) + j) * COL + ay) * COL + ax;
            const float o0 = o[base];
            const float o1 = o[base + (size_t)NJ * PAIR_ELEMS];
            const float o2 = o[base + (size_t)(2 * NJ) * PAIR_ELEMS];
            const float scale = 1.0f / (float)COL;
            const float dx = (o0 + (float)ax * scale) - t0;
            const float dy = (o1 + (float)ay * scale) - t1;
            const float dz = o2 - t2;
            acc += dx * dx + dy * dy + dz * dz;
        }
    }

    // ---- block reduction ----
    #pragma unroll
    for (int off = 16; off > 0; off >>= 1)
        acc += __shfl_down_sync(0xffffffffu, acc, off);
    if (lane == 0) wsum[warp] = acc;
    __syncthreads();

    if (warp == 0) {
        float s = (lane < WARPS_PER_BLOCK) ? wsum[lane] : 0.0f;
        #pragma unroll
        for (int off = WARPS_PER_BLOCK / 2; off > 0; off >>= 1)
            s += __shfl_down_sync(0xffffffffu, s, off);
        if (lane == 0) {
            atomicAdd(&g_sum, s * (1.0f / (float)NJ));
            __threadfence();
            unsigned int done = atomicAdd(&g_count, 1u);
            if (done == gridDim.x - 1) {
                // last block: publish result and reset for next (graph-replayed) run
                float total = atomicExch(&g_sum, 0.0f);
                out[0] = total;
                g_count = 0u;
                __threadfence();
            }
        }
    }
}

extern "C" void kernel_launch(void* const* d_in, const int* in_sizes, int n_in,
                              void* d_out, int out_size) {
    const float* o = (const float*)d_in[0];
    const float* h = (const float*)d_in[1];
    const float* t = (const float*)d_in[2];
    const int*   v = (const int*)d_in[3];
    float* out = (float*)d_out;

    const int n_pairs = in_sizes[1] / PAIR_ELEMS;   // B * NJ from h
    const int blocks  = (n_pairs + WARPS_PER_BLOCK - 1) / WARPS_PER_BLOCK;

    mse3d_kernel<<<blocks, BLOCK_THREADS>>>(o, h, t, v, out, n_pairs);
}

// round 3
// speedup vs baseline: 1.5872x; 1.2735x over previous
#include <cuda_runtime.h>
#include <math.h>

#define COL 14
#define NJ 23
#define PAIR_ELEMS (COL * COL)   // 196
#define WARPS_PER_BLOCK 16
#define BLOCK_THREADS (WARPS_PER_BLOCK * 32)
#define PAIRS_PER_WARP 8

__device__ float        g_sum   = 0.0f;
__device__ unsigned int g_count = 0u;

// gaussian weights exp(-k^2/2)/sum, k=-4..4, normalized in double then cast to f32
__device__ __constant__ float c_w[9] = {
    0.000133832f, 0.00443186f, 0.05399111f, 0.24197140f, 0.39894345f,
    0.24197140f, 0.05399111f, 0.00443186f, 0.000133832f
};

__global__ __launch_bounds__(BLOCK_THREADS)
void mse3d_kernel(const float* __restrict__ o,
                  const float* __restrict__ h,
                  const float* __restrict__ t,
                  const int*   __restrict__ v,
                  float* __restrict__ out,
                  int n_pairs, int nblocks) {
    // sMt[i*COL + r] = M[r][i]  (column i of M contiguous)
    __shared__ float sMt[PAIR_ELEMS];
    __shared__ float sColMin[COL], sColMax[COL];
    __shared__ float wsum[WARPS_PER_BLOCK];

    const int tid = threadIdx.x;

    // ---- per-block gaussian matrix build (hardcoded weights, ~50 instr) ----
    if (tid < PAIR_ELEMS) {
        const int outr = tid / COL;
        const int i    = tid % COL;
        float m = 0.0f;
        #pragma unroll
        for (int k = -4; k <= 4; k++) {
            int ii = (outr + k + 2 * COL) % (2 * COL);
            if (ii >= COL) ii = 2 * COL - 1 - ii;
            if (ii == i) m += c_w[k + 4];
        }
        sMt[i * COL + outr] = m;
    }
    __syncthreads();
    if (tid < COL) {
        float mn = INFINITY, mx = -INFINITY;
        #pragma unroll
        for (int r = 0; r < COL; r++) {
            float val = sMt[tid * COL + r];   // M[r][tid]
            mn = fminf(mn, val);
            mx = fmaxf(mx, val);
        }
        sColMin[tid] = mn;
        sColMax[tid] = mx;
    }
    __syncthreads();

    const int lane = tid & 31;
    const int warp = tid >> 5;
    const int gwarp = blockIdx.x * WARPS_PER_BLOCK + warp;
    const int pair0 = gwarp * PAIRS_PER_WARP;

    float acc = 0.0f;

    #pragma unroll 2
    for (int p = 0; p < PAIRS_PER_WARP; p++) {
        const int pair = pair0 + p;
        if (pair >= n_pairs) break;

        // ---- vectorized load of h tile: 49 float4 per pair ----
        const float4* hp4 = (const float4*)(h + (size_t)pair * PAIR_ELEMS);
        const int  ia   = lane;            // < 49 always
        const int  ib   = 32 + lane;
        const bool hasb = (ib < 49);       // lanes 0..16
        float4 va = hp4[ia];
        float4 vb = hasb ? hp4[ib] : make_float4(0.f, 0.f, 0.f, 0.f);

        // per-pair scalars (broadcast loads), issued early
        const float t0 = t[(size_t)pair * 3 + 0];
        const float t1 = t[(size_t)pair * 3 + 1];
        const float t2 = t[(size_t)pair * 3 + 2];
        const int   vv = v[(size_t)pair * 2];

        // ---- local argmax (ascending order, strict > keeps first occurrence) ----
        float best = va.x; int bidx = 4 * ia;
        if (va.y > best) { best = va.y; bidx = 4 * ia + 1; }
        if (va.z > best) { best = va.z; bidx = 4 * ia + 2; }
        if (va.w > best) { best = va.w; bidx = 4 * ia + 3; }
        if (hasb) {
            if (vb.x > best) { best = vb.x; bidx = 4 * ib; }
            if (vb.y > best) { best = vb.y; bidx = 4 * ib + 1; }
            if (vb.z > best) { best = vb.z; bidx = 4 * ib + 2; }
            if (vb.w > best) { best = vb.w; bidx = 4 * ib + 3; }
        }
        // h >= 0 (uniform[0,1)) so float bits are order-isomorphic to values:
        // redux-max on bits, then redux-min on index among maximal lanes.
        const unsigned int bbits = __float_as_uint(best);
        const unsigned int mbits = __reduce_max_sync(0xffffffffu, bbits);
        const int amax = (int)__reduce_min_sync(
            0xffffffffu, (bbits == mbits) ? (unsigned)bidx : 0xffffffffu);
        const int ay = amax / COL;
        const int ax = amax - ay * COL;

        // ---- mask / normalization params ----
        const int xi = (int)truncf(t0 * (float)COL);
        const int yi = (int)truncf(t1 * (float)COL);
        const bool in_range = (xi >= 0) && (xi <= COL - 1) && (yi >= 0) && (yi <= COL - 1);
        const bool mask = (vv == 1) && in_range;

        if (mask) {
            const int xc = min(max(xi, 0), COL - 1);
            const int yc = min(max(yi, 0), COL - 1);
            const float mn  = sColMin[yc] * sColMin[xc];
            const float mx  = sColMax[yc] * sColMax[xc];
            const float inv = 1.0f / (mx - mn);
            const float nb  = -mn * inv;              // ttv = gy*gx*inv + nb
            const float* gy = &sMt[yc * COL];         // gy[r] = M[r][yc]
            const float* gx = &sMt[xc * COL];         // gx[c] = M[c][xc]

            {
                int e = 4 * ia;
                int r = e / COL, c = e - (e / COL) * COL;
                float hv[4] = {va.x, va.y, va.z, va.w};
                #pragma unroll
                for (int q = 0; q < 4; q++) {
                    float ttv = fmaf(gy[r] * gx[c], inv, nb);
                    float d = hv[q] - ttv;
                    acc = fmaf(d, d, acc);
                    if (++c == COL) { c = 0; ++r; }
                }
            }
            if (hasb) {
                int e = 4 * ib;
                int r = e / COL, c = e - (e / COL) * COL;
                float hv[4] = {vb.x, vb.y, vb.z, vb.w};
                #pragma unroll
                for (int q = 0; q < 4; q++) {
                    float ttv = fmaf(gy[r] * gx[c], inv, nb);
                    float d = hv[q] - ttv;
                    acc = fmaf(d, d, acc);
                    if (++c == COL) { c = 0; ++r; }
                }
            }
        } else {
            // tt == 0 everywhere: contribution is just sum(h^2)
            acc = fmaf(va.x, va.x, acc);
            acc = fmaf(va.y, va.y, acc);
            acc = fmaf(va.z, va.z, acc);
            acc = fmaf(va.w, va.w, acc);
            if (hasb) {
                acc = fmaf(vb.x, vb.x, acc);
                acc = fmaf(vb.y, vb.y, acc);
                acc = fmaf(vb.z, vb.z, acc);
                acc = fmaf(vb.w, vb.w, acc);
            }
        }

        // ---- d2: 3 gathered values from o (lane 0 only) ----
        if (lane == 0) {
            const int b = pair / NJ;
            const int j = pair - b * NJ;
            const size_t base = (((size_t)b * (3 * NJ) + j) * COL + ay) * COL + ax;
            const float o0 = o[base];
            const float o1 = o[base + (size_t)NJ * PAIR_ELEMS];
            const float o2 = o[base + (size_t)(2 * NJ) * PAIR_ELEMS];
            const float scale = 1.0f / (float)COL;
            const float dx = (o0 + (float)ax * scale) - t0;
            const float dy = (o1 + (float)ay * scale) - t1;
            const float dz = o2 - t2;
            acc += dx * dx + dy * dy + dz * dz;
        }
    }

    // ---- block reduction ----
    #pragma unroll
    for (int off = 16; off > 0; off >>= 1)
        acc += __shfl_down_sync(0xffffffffu, acc, off);
    if (lane == 0) wsum[warp] = acc;
    __syncthreads();

    if (warp == 0) {
        float s = (lane < WARPS_PER_BLOCK) ? wsum[lane] : 0.0f;
        #pragma unroll
        for (int off = WARPS_PER_BLOCK / 2; off > 0; off >>= 1)
            s += __shfl_down_sync(0xffffffffu, s, off);
        if (lane == 0) {
            atomicAdd(&g_sum, s * (1.0f / (float)NJ));
            __threadfence();
            unsigned int done = atomicAdd(&g_count, 1u);
            if (done == (unsigned)nblocks - 1) {
                float total = atomicExch(&g_sum, 0.0f);
                out[0] = total;
                g_count = 0u;
                __threadfence();
            }
        }
    }
}

extern "C" void kernel_launch(void* const* d_in, const int* in_sizes, int n_in,
                              void* d_out, int out_size) {
    const float* o = (const float*)d_in[0];
    const float* h = (const float*)d_in[1];
    const float* t = (const float*)d_in[2];
    const int*   v = (const int*)d_in[3];
    float* out = (float*)d_out;

    const int n_pairs = in_sizes[1] / PAIR_ELEMS;   // B * NJ from h
    const int pairs_per_block = WARPS_PER_BLOCK * PAIRS_PER_WARP;
    const int blocks = (n_pairs + pairs_per_block - 1) / pairs_per_block;

    mse3d_kernel<<<blocks, BLOCK_THREADS>>>(o, h, t, v, out, n_pairs, blocks);
}

// round 4
// speedup vs baseline: 1.9027x; 1.1988x over previous
#include <cuda_runtime.h>
#include <math.h>

#define COL 14
#define NJ 23
#define PAIR_ELEMS (COL * COL)   // 196
#define WARPS_PER_BLOCK 8
#define BLOCK_THREADS (WARPS_PER_BLOCK * 32)
#define GRID_BLOCKS (148 * 8)    // one full wave at 8 blocks/SM

__device__ float        g_sum   = 0.0f;
__device__ unsigned int g_count = 0u;

// gaussian weights exp(-k^2/2)/sum, k=-4..4 (normalized in double, cast to f32)
__device__ __constant__ float c_w[9] = {
    0.000133832f, 0.00443186f, 0.05399111f, 0.24197140f, 0.39894345f,
    0.24197140f, 0.05399111f, 0.00443186f, 0.000133832f
};

__global__ __launch_bounds__(BLOCK_THREADS, 8)
void mse3d_kernel(const float* __restrict__ o,
                  const float* __restrict__ h,
                  const float* __restrict__ t,
                  const int*   __restrict__ v,
                  float* __restrict__ out,
                  int n_pairs, int total_warps, int nblocks) {
    // sMt[i*COL + r] = M[r][i]  (column i of M contiguous)
    __shared__ float sMt[PAIR_ELEMS];
    __shared__ float sColMin[COL], sColMax[COL];
    __shared__ float wsum[WARPS_PER_BLOCK];

    const int tid = threadIdx.x;

    // ---- per-block gaussian matrix build ----
    if (tid < PAIR_ELEMS) {
        const int outr = tid / COL;
        const int i    = tid % COL;
        float m = 0.0f;
        #pragma unroll
        for (int k = -4; k <= 4; k++) {
            int ii = (outr + k + 2 * COL) % (2 * COL);
            if (ii >= COL) ii = 2 * COL - 1 - ii;
            if (ii == i) m += c_w[k + 4];
        }
        sMt[i * COL + outr] = m;
    }
    __syncthreads();
    if (tid < COL) {
        float mn = INFINITY, mx = -INFINITY;
        #pragma unroll
        for (int r = 0; r < COL; r++) {
            float val = sMt[tid * COL + r];   // M[r][tid]
            mn = fminf(mn, val);
            mx = fmaxf(mx, val);
        }
        sColMin[tid] = mn;
        sColMax[tid] = mx;
    }
    __syncthreads();

    const int lane  = tid & 31;
    const int warp  = tid >> 5;
    const int gwarp = blockIdx.x * WARPS_PER_BLOCK + warp;

    float acc  = 0.0f;   // d1 chain (h only)
    float acc2 = 0.0f;   // d2 chain (o gathers) — kept separate so the d1 FMA
                         // chain never waits on the dependent o-gather latency

    for (int pair = gwarp; pair < n_pairs; pair += total_warps) {
        // ---- vectorized load of h tile: 49 float4 per pair ----
        const float4* hp4 = (const float4*)(h + (size_t)pair * PAIR_ELEMS);
        const int  ia   = lane;            // < 49 always
        const int  ib   = 32 + lane;
        const bool hasb = (ib < 49);       // lanes 0..16
        float4 va = hp4[ia];
        float4 vb = hasb ? hp4[ib] : make_float4(0.f, 0.f, 0.f, 0.f);

        // per-pair scalars (broadcast loads), issued early
        const float t0 = t[(size_t)pair * 3 + 0];
        const float t1 = t[(size_t)pair * 3 + 1];
        const float t2 = t[(size_t)pair * 3 + 2];
        const int   vv = v[(size_t)pair * 2];

        // ---- local argmax (ascending order, strict > keeps first occurrence) ----
        float best = va.x; int bidx = 4 * ia;
        if (va.y > best) { best = va.y; bidx = 4 * ia + 1; }
        if (va.z > best) { best = va.z; bidx = 4 * ia + 2; }
        if (va.w > best) { best = va.w; bidx = 4 * ia + 3; }
        if (hasb) {
            if (vb.x > best) { best = vb.x; bidx = 4 * ib; }
            if (vb.y > best) { best = vb.y; bidx = 4 * ib + 1; }
            if (vb.z > best) { best = vb.z; bidx = 4 * ib + 2; }
            if (vb.w > best) { best = vb.w; bidx = 4 * ib + 3; }
        }
        // h >= 0 so float bits are order-isomorphic: redux-max on bits,
        // then redux-min on index among maximal lanes (first occurrence).
        const unsigned int bbits = __float_as_uint(best);
        const unsigned int mbits = __reduce_max_sync(0xffffffffu, bbits);
        const int amax = (int)__reduce_min_sync(
            0xffffffffu, (bbits == mbits) ? (unsigned)bidx : 0xffffffffu);
        const int ay = amax / COL;
        const int ax = amax - ay * COL;

        // ---- d2: 3 gathered values from o (lane 0 only), separate chain ----
        if (lane == 0) {
            const int b = pair / NJ;
            const int j = pair - b * NJ;
            const size_t base = (((size_t)b * (3 * NJ) + j) * COL + ay) * COL + ax;
            const float o0 = o[base];
            const float o1 = o[base + (size_t)NJ * PAIR_ELEMS];
            const float o2 = o[base + (size_t)(2 * NJ) * PAIR_ELEMS];
            const float scale = 1.0f / (float)COL;
            const float dx = (o0 + (float)ax * scale) - t0;
            const float dy = (o1 + (float)ay * scale) - t1;
            const float dz = o2 - t2;
            acc2 += dx * dx + dy * dy + dz * dz;
        }

        // ---- mask / normalization params ----
        const int xi = (int)truncf(t0 * (float)COL);
        const int yi = (int)truncf(t1 * (float)COL);
        const bool in_range = (xi >= 0) && (xi <= COL - 1) && (yi >= 0) && (yi <= COL - 1);
        const bool mask = (vv == 1) && in_range;

        if (mask) {
            const int xc = min(max(xi, 0), COL - 1);
            const int yc = min(max(yi, 0), COL - 1);
            const float mn  = sColMin[yc] * sColMin[xc];
            const float mx  = sColMax[yc] * sColMax[xc];
            const float inv = 1.0f / (mx - mn);
            const float nb  = -mn * inv;              // ttv = gy*gx*inv + nb
            const float* gy = &sMt[yc * COL];         // gy[r] = M[r][yc]
            const float* gx = &sMt[xc * COL];         // gx[c] = M[c][xc]

            {
                int e = 4 * ia;
                int r = e / COL, c = e - (e / COL) * COL;
                float hv[4] = {va.x, va.y, va.z, va.w};
                #pragma unroll
                for (int q = 0; q < 4; q++) {
                    float ttv = fmaf(gy[r] * gx[c], inv, nb);
                    float d = hv[q] - ttv;
                    acc = fmaf(d, d, acc);
                    if (++c == COL) { c = 0; ++r; }
                }
            }
            if (hasb) {
                int e = 4 * ib;
                int r = e / COL, c = e - (e / COL) * COL;
                float hv[4] = {vb.x, vb.y, vb.z, vb.w};
                #pragma unroll
                for (int q = 0; q < 4; q++) {
                    float ttv = fmaf(gy[r] * gx[c], inv, nb);
                    float d = hv[q] - ttv;
                    acc = fmaf(d, d, acc);
                    if (++c == COL) { c = 0; ++r; }
                }
            }
        } else {
            // tt == 0 everywhere: contribution is just sum(h^2)
            acc = fmaf(va.x, va.x, acc);
            acc = fmaf(va.y, va.y, acc);
            acc = fmaf(va.z, va.z, acc);
            acc = fmaf(va.w, va.w, acc);
            if (hasb) {
                acc = fmaf(vb.x, vb.x, acc);
                acc = fmaf(vb.y, vb.y, acc);
                acc = fmaf(vb.z, vb.z, acc);
                acc = fmaf(vb.w, vb.w, acc);
            }
        }
    }

    acc += acc2;

    // ---- block reduction ----
    #pragma unroll
    for (int off = 16; off > 0; off >>= 1)
        acc += __shfl_down_sync(0xffffffffu, acc, off);
    if (lane == 0) wsum[warp] = acc;
    __syncthreads();

    if (warp == 0) {
        float s = (lane < WARPS_PER_BLOCK) ? wsum[lane] : 0.0f;
        #pragma unroll
        for (int off = WARPS_PER_BLOCK / 2; off > 0; off >>= 1)
            s += __shfl_down_sync(0xffffffffu, s, off);
        if (lane == 0) {
            atomicAdd(&g_sum, s * (1.0f / (float)NJ));
            __threadfence();
            unsigned int done = atomicAdd(&g_count, 1u);
            if (done == (unsigned)nblocks - 1) {
                float total = atomicExch(&g_sum, 0.0f);
                out[0] = total;
                g_count = 0u;
                __threadfence();
            }
        }
    }
}

extern "C" void kernel_launch(void* const* d_in, const int* in_sizes, int n_in,
                              void* d_out, int out_size) {
    const float* o = (const float*)d_in[0];
    const float* h = (const float*)d_in[1];
    const float* t = (const float*)d_in[2];
    const int*   v = (const int*)d_in[3];
    float* out = (float*)d_out;

    const int n_pairs = in_sizes[1] / PAIR_ELEMS;   // B * NJ from h

    int blocks = GRID_BLOCKS;
    int max_needed = (n_pairs + WARPS_PER_BLOCK - 1) / WARPS_PER_BLOCK;
    if (blocks > max_needed) blocks = max_needed;
    const int total_warps = blocks * WARPS_PER_BLOCK;

    mse3d_kernel<<<blocks, BLOCK_THREADS>>>(o, h, t, v, out,
                                            n_pairs, total_warps, blocks);
}